// round 13
// baseline (speedup 1.0000x reference)
#include <cuda_runtime.h>
#include <math.h>
#include <float.h>

// Problem constants (fixed by setup_inputs)
#define BMAX 2
#define NMAX 8192
#define GMAX 96
#define KMAX 128
#define RAD  0.1f
#define RAD2 0.01f      // float32 nearest to python 0.1*0.1 (matches JAX)
#define CMAXF 8192      // max flattened cells supported (data -> gdprod = 1000)
#define SBLK 8          // sort blocks per batch: 8 x 1024 = 1 thread / particle

struct GridInfo {
    float lx, ly, lz;
    int g0, g1, g2;
    int s0, s1;
    int gdprod;
};

struct MM { unsigned mn[3]; unsigned mx[3]; };

__device__ GridInfo     g_grid[BMAX];
__device__ MM           g_mm[BMAX];
__device__ int          g_hist[BMAX][CMAXF];
__device__ int          g_ofs[BMAX][CMAXF];
__device__ int          g_sidx[BMAX][NMAX];
__device__ int          g_idx[BMAX][NMAX];
__device__ float4       g_nlocs[BMAX][NMAX];
__device__ int          g_start[BMAX][CMAXF + 1];
__device__ int          g_bar_cnt[BMAX];          // zero-init, self-resetting
__device__ volatile int g_bar_gen[BMAX];          // monotone generation

// Monotone float<->uint map (order-preserving; atomic min/max = exact min/max)
__device__ __forceinline__ unsigned fenc(float f) {
    unsigned u = __float_as_uint(f);
    return (u & 0x80000000u) ? ~u : (u | 0x80000000u);
}
__device__ __forceinline__ float fdec(unsigned u) {
    unsigned b2 = (u & 0x80000000u) ? (u & 0x7FFFFFFFu) : ~u;
    return __uint_as_float(b2);
}

// Per-batch grid barrier across SBLK co-resident blocks (generation-based,
// reusable, graph-replay safe: cnt returns to 0, gen just keeps counting).
__device__ __forceinline__ void batch_barrier(int b)
{
    __syncthreads();
    if (threadIdx.x == 0) {
        __threadfence();
        int gen = g_bar_gen[b];
        if (atomicAdd(&g_bar_cnt[b], 1) == SBLK - 1) {
            g_bar_cnt[b] = 0;
            __threadfence();
            g_bar_gen[b] = gen + 1;
        } else {
            while (g_bar_gen[b] == gen) { __nanosleep(32); }
        }
        __threadfence();
    }
    __syncthreads();
}

// ---------------------------------------------------------------------------
// Wide sort: SBLK blocks per batch, 1 thread per particle, phases separated
// by the spin barrier (mechanism proven in R6's persistent kernel).
// ---------------------------------------------------------------------------
__global__ __launch_bounds__(1024)
void sort_kernel(const float* __restrict__ locs, int N)
{
    __shared__ int   s_idx[NMAX];            // 32KB: scan scratch + slice fixup
    __shared__ float s_wmn[32][3], s_wmx[32][3];
    __shared__ int   s_part[32];

    const int b    = blockIdx.x / SBLK;
    const int r    = blockIdx.x % SBLK;
    const int t    = threadIdx.x;
    const int lane = t & 31;
    const int wid  = t >> 5;
    const int gid  = r * 1024 + t;

    // ---- phase 0: reset hist + minmax sentinels ----
    if (gid < CMAXF) g_hist[b][gid] = 0;
    if (r == 0 && t < 3) {
        g_mm[b].mn[t] = 0xFFFFFFFFu;
        g_mm[b].mx[t] = 0u;
    }
    batch_barrier(b);

    // ---- phase 1: load particle, block-reduce min/max, 6 atomics / block ----
    const bool act = (gid < N);
    float px = 0.f, py = 0.f, pz = 0.f;
    if (act) {
        const float* p = locs + ((size_t)b * N + gid) * 3;
        px = p[0]; py = p[1]; pz = p[2];
    }
    {
        float mn[3] = { act ? px : FLT_MAX, act ? py : FLT_MAX, act ? pz : FLT_MAX };
        float mx[3] = { act ? px : -FLT_MAX, act ? py : -FLT_MAX, act ? pz : -FLT_MAX };
        #pragma unroll
        for (int d = 0; d < 3; d++) {
            #pragma unroll
            for (int o = 16; o > 0; o >>= 1) {
                mn[d] = fminf(mn[d], __shfl_down_sync(0xffffffffu, mn[d], o));
                mx[d] = fmaxf(mx[d], __shfl_down_sync(0xffffffffu, mx[d], o));
            }
            if (lane == 0) { s_wmn[wid][d] = mn[d]; s_wmx[wid][d] = mx[d]; }
        }
        __syncthreads();
        if (wid == 0) {
            float a[3], z[3];
            #pragma unroll
            for (int d = 0; d < 3; d++) { a[d] = s_wmn[lane][d]; z[d] = s_wmx[lane][d]; }
            #pragma unroll
            for (int d = 0; d < 3; d++) {
                #pragma unroll
                for (int o = 16; o > 0; o >>= 1) {
                    a[d] = fminf(a[d], __shfl_down_sync(0xffffffffu, a[d], o));
                    z[d] = fmaxf(z[d], __shfl_down_sync(0xffffffffu, z[d], o));
                }
                if (lane == 0) {
                    atomicMin(&g_mm[b].mn[d], fenc(a[d]));
                    atomicMax(&g_mm[b].mx[d], fenc(z[d]));
                }
            }
        }
    }
    batch_barrier(b);

    // ---- phase 2: grid info (redundant, deterministic) + cid + histogram ----
    float lo[3];
    int   g[3];
    #pragma unroll
    for (int d = 0; d < 3; d++) {
        float l = fdec(g_mm[b].mn[d]);
        float h = fdec(g_mm[b].mx[d]);
        lo[d] = l;
        int gg = (int)floorf(__fdiv_rn(__fsub_rn(h, l), RAD)) + 1;
        g[d] = max(1, min(GMAX, gg));
    }
    const int st1 = g[2];
    const int st0 = g[1] * g[2];
    int gdp = g[0] * g[1] * g[2];
    if (gdp > CMAXF) gdp = CMAXF;       // never hit for [0,1)^3 data
    if (r == 0 && t == 0) {
        GridInfo gi;
        gi.lx = lo[0]; gi.ly = lo[1]; gi.lz = lo[2];
        gi.g0 = g[0]; gi.g1 = g[1]; gi.g2 = g[2];
        gi.s0 = st0; gi.s1 = st1; gi.gdprod = gdp;
        g_grid[b] = gi;
    }
    int cid = 0;
    if (act) {
        float v[3] = { px, py, pz };
        int c[3];
        #pragma unroll
        for (int d = 0; d < 3; d++) {
            int cc = (int)floorf(__fdiv_rn(__fsub_rn(v[d], lo[d]), RAD));
            c[d] = max(0, min(g[d] - 1, cc));
        }
        cid = c[0] * st0 + c[1] * st1 + c[2];
        if (cid >= gdp) cid = gdp - 1;
        atomicAdd(&g_hist[b][cid], 1);
    }
    batch_barrier(b);

    // ---- phase 3: exclusive scan (block r==0 only) -> g_start, g_ofs ----
    if (r == 0) {
        if (gdp <= 1024) {
            int v = (t < gdp) ? g_hist[b][t] : 0;
            int x = v;
            #pragma unroll
            for (int o = 1; o < 32; o <<= 1) {
                int y = __shfl_up_sync(0xffffffffu, x, o);
                if (lane >= o) x += y;
            }
            if (lane == 31) s_part[wid] = x;
            __syncthreads();
            if (wid == 0) {
                int w2 = s_part[lane];
                int xw = w2;
                #pragma unroll
                for (int o = 1; o < 32; o <<= 1) {
                    int y = __shfl_up_sync(0xffffffffu, xw, o);
                    if (lane >= o) xw += y;
                }
                s_part[lane] = xw - w2;
            }
            __syncthreads();
            int excl = x - v + s_part[wid];
            if (t < gdp) { g_start[b][t] = excl; g_ofs[b][t] = excl; }
            if (t == 0) g_start[b][gdp] = N;
        } else {
            // general path: Hillis-Steele over thread chunks (s_idx as scratch)
            const int E = (gdp + 1023) >> 10;   // <= 8
            int vals[8];
            int base = t * E;
            int sum = 0;
            #pragma unroll 8
            for (int e = 0; e < 8; e++) {
                int c = base + e;
                int v = (e < E && c < gdp) ? g_hist[b][c] : 0;
                vals[e] = v; sum += v;
            }
            s_idx[t] = sum;
            __syncthreads();
            for (int off = 1; off < 1024; off <<= 1) {
                int v = (t >= off) ? s_idx[t - off] : 0;
                __syncthreads();
                s_idx[t] += v;
                __syncthreads();
            }
            int run = s_idx[t] - sum;
            #pragma unroll 8
            for (int e = 0; e < 8; e++) {
                int c = base + e;
                if (e < E && c < gdp) { g_start[b][c] = run; g_ofs[b][c] = run; run += vals[e]; }
            }
            if (t == 0) g_start[b][gdp] = N;
        }
    }
    batch_barrier(b);

    // ---- phase 4: scatter (unordered within cell) ----
    if (act) {
        int pos = atomicAdd(&g_ofs[b][cid], 1);
        g_sidx[b][pos] = gid;
    }
    batch_barrier(b);

    // ---- phase 5: per-block smem slice fixup (stable) + emit ----
    {
        int cpc = (gdp + SBLK - 1) / SBLK;
        int c0 = min(r * cpc, gdp);
        int c1 = min(c0 + cpc, gdp);
        int plo = 0, phi = 0;
        if (c0 < c1) { plo = g_start[b][c0]; phi = g_start[b][c1]; }
        int count = phi - plo;

        for (int k = t; k < count; k += 1024)
            s_idx[k] = g_sidx[b][plo + k];
        __syncthreads();

        // insertion sort each cell's slice by original index => exact STABLE
        for (int c = c0 + t; c < c1; c += 1024) {
            int lo2 = g_start[b][c] - plo;
            int hi2 = g_start[b][c + 1] - plo;
            for (int i = lo2 + 1; i < hi2; i++) {
                int v = s_idx[i];
                int j = i - 1;
                while (j >= lo2 && s_idx[j] > v) { s_idx[j + 1] = s_idx[j]; j--; }
                s_idx[j + 1] = v;
            }
        }
        __syncthreads();

        const float* L = locs + (size_t)b * N * 3;
        for (int k = t; k < count; k += 1024) {
            int i = s_idx[k];
            int pos = plo + k;
            g_idx[b][pos] = i;
            float x = L[i * 3 + 0];
            float y = L[i * 3 + 1];
            float z = L[i * 3 + 2];
            g_nlocs[b][pos] = make_float4(x, y, z, 0.f);
        }
    }
}

// ---------------------------------------------------------------------------
// Fused tail (byte-identical logic to R10's proven 18.75us version):
// [collide blocks | emit blocks | gather blocks]
// ---------------------------------------------------------------------------
__global__ void tail_kernel(const float4* __restrict__ data,
                            const float* __restrict__ qlocs,
                            float* __restrict__ out_nlocs,
                            float4* __restrict__ out_ndata,
                            float* __restrict__ out_idxs,
                            float* __restrict__ out_nb,
                            int B, int N, int C4, int M,
                            int collideBlocks, int emitBlocks)
{
    int bx = blockIdx.x;
    if (bx >= collideBlocks) {
        bx -= collideBlocks;
        if (bx < emitBlocks) {
            // -------- emit out_idxs + out_nlocs from g_idx/g_nlocs --------
            int t = bx * blockDim.x + threadIdx.x;
            if (t >= B * N) return;
            int b = t / N, pos = t - b * N;
            float4 p = g_nlocs[b][pos];
            float* o = out_nlocs + (size_t)t * 3;
            o[0] = p.x; o[1] = p.y; o[2] = p.z;
            out_idxs[t] = (float)__ldg(&g_idx[b][pos]);
            return;
        }
        // ---------------- gather: 4 float4s per thread ----------------
        int Q = C4 >> 2;
        int t = (bx - emitBlocks) * blockDim.x + threadIdx.x;
        if (t >= B * N * Q) return;
        int sub = t % Q;
        int bi  = t / Q;
        int b = bi / N, i = bi - b * N;
        int idx = __ldg(&g_idx[b][i]);
        const float4* src = data + (((size_t)b * N + idx) * C4) + sub * 4;
        float4* dst = out_ndata + ((size_t)bi * C4) + sub * 4;
        float4 v0 = src[0], v1 = src[1], v2 = src[2], v3 = src[3];
        dst[0] = v0; dst[1] = v1; dst[2] = v2; dst[3] = v3;
        return;
    }

    // ---------------- collide: one warp per query ----------------
    int gt   = blockIdx.x * blockDim.x + threadIdx.x;
    int w    = gt >> 5;
    int lane = gt & 31;
    if (w >= B * M) return;
    int b = w / M, m = w - b * M;

    const float* q = qlocs + ((size_t)b * M + m) * 3;
    float qx = q[0], qy = q[1], qz = q[2];

    GridInfo gi = g_grid[b];
    int cqx = (int)floorf(__fdiv_rn(__fsub_rn(qx, gi.lx), RAD));
    int cqy = (int)floorf(__fdiv_rn(__fsub_rn(qy, gi.ly), RAD));
    int cqz = (int)floorf(__fdiv_rn(__fsub_rn(qz, gi.lz), RAD));
    int z0 = max(0, cqz - 1), z1 = min(gi.g2 - 1, cqz + 1);

    const int* __restrict__ S = g_start[b];
    const float4* __restrict__ P = g_nlocs[b];
    float* outp = out_nb + (size_t)w * KMAX;

    // prefill whole row with -1 (one float4 per lane), hits overwrite below
    ((float4*)outp)[lane] = make_float4(-1.f, -1.f, -1.f, -1.f);
    __syncwarp();

    // segment bounds (18 concurrent LDGs, fully unrolled predicated)
    int jlo[9], jhi[9];
    bool zok = (z0 <= z1);
    #pragma unroll
    for (int r = 0; r < 9; r++) {
        int cx = cqx + (r / 3) - 1;
        int cy = cqy + (r % 3) - 1;
        bool ok = zok && cx >= 0 && cx < gi.g0 && cy >= 0 && cy < gi.g1;
        int base = cx * gi.s0 + cy * gi.s1;
        jlo[r] = ok ? S[base + z0] : 0;
        jhi[r] = ok ? S[base + z1 + 1] : 0;
    }

    int cnt = 0;
    bool done = false;
    #pragma unroll
    for (int r = 0; r < 9; r++) {
        int lo = jlo[r], hi = jhi[r];
        for (int j0 = lo; j0 < hi && !done; j0 += 32) {
            int j = j0 + lane;
            bool hit = false;
            if (j < hi) {
                float4 p = P[j];
                float dx = __fsub_rn(qx, p.x);
                float dy = __fsub_rn(qy, p.y);
                float dz = __fsub_rn(qz, p.z);
                float d2 = __fadd_rn(__fadd_rn(__fmul_rn(dx, dx),
                                               __fmul_rn(dy, dy)),
                                     __fmul_rn(dz, dz));
                hit = (d2 <= RAD2);
            }
            unsigned msk = __ballot_sync(0xffffffffu, hit);
            if (hit) {
                int pos = cnt + __popc(msk & ((1u << lane) - 1u));
                if (pos < KMAX) outp[pos] = (float)j;
            }
            cnt += __popc(msk);
            if (cnt >= KMAX) { cnt = KMAX; done = true; }
        }
        if (done) break;
    }
}

// ---------------------------------------------------------------------------
extern "C" void kernel_launch(void* const* d_in, const int* in_sizes, int n_in,
                              void* d_out, int out_size)
{
    const float* locs  = (const float*)d_in[0];
    const float* data  = (const float*)d_in[1];
    const float* qlocs = (const float*)d_in[2];

    const int B = 2;                       // fixed by setup_inputs
    const int N = in_sizes[0] / (B * 3);
    const int C = in_sizes[1] / (B * N);
    const int M = in_sizes[2] / (B * 3);
    if (N > NMAX || B > BMAX) return;      // scratch bound guard (never hit)

    float* out       = (float*)d_out;
    float* out_nlocs = out;
    float* out_ndata = out_nlocs + (size_t)B * N * 3;
    float* out_idxs  = out_ndata + (size_t)B * N * C;
    float* out_nb    = out_idxs  + (size_t)B * N;

    sort_kernel<<<B * SBLK, 1024>>>(locs, N);

    const int TPB = 256;
    int C4 = C / 4;
    int Q  = C4 / 4;
    int collideBlocks = (B * M * 32 + TPB - 1) / TPB;
    int emitBlocks    = (B * N + TPB - 1) / TPB;
    int gatherBlocks  = (B * N * Q + TPB - 1) / TPB;
    tail_kernel<<<collideBlocks + emitBlocks + gatherBlocks, TPB>>>(
        (const float4*)data, qlocs, out_nlocs, (float4*)out_ndata,
        out_idxs, out_nb, B, N, C4, M, collideBlocks, emitBlocks);
}

// round 14
// speedup vs baseline: 1.1531x; 1.1531x over previous
#include <cuda_runtime.h>
#include <math.h>
#include <float.h>

// Problem constants (fixed by setup_inputs)
#define BMAX 2
#define NMAX 8192
#define GMAX 96
#define KMAX 128
#define RAD  0.1f
#define RAD2 0.01f      // float32 nearest to python 0.1*0.1 (matches JAX)
#define BCELLS 1728     // max flattened cells in bucket sort (data: 10^3=1000)
#define BCAP 32         // bucket capacity (Poisson(8.2): P(>32) ~ 3e-8)

struct GridInfo {
    float lx, ly, lz;
    int g0, g1, g2;
    int s0, s1;
    int gdprod;
};

__device__ GridInfo g_grid[BMAX];
__device__ int      g_idx[BMAX][NMAX];
__device__ float4   g_nlocs[BMAX][NMAX];
__device__ int      g_start[BMAX][BCELLS + 1];

// ---------------------------------------------------------------------------
// Fused sort kernel: one block per batch, 1024 threads, all phases in smem.
// Bucket counting sort: ONE atomic pass (slot = atomicAdd on cell counter,
// particle idx written into per-cell u16 bucket). Counters double as the
// histogram. Per-cell insertion sort (ascending original index) restores the
// exact STABLE argsort order.
// smem: loc[3N] | cnt[BCELLS] | start[BCELLS+1] | bkt[BCELLS*BCAP] u16
//       = 96K + 6.75K + 6.75K + 108K  ~= 218KB dynamic
// ---------------------------------------------------------------------------
__global__ __launch_bounds__(1024)
void sort_kernel(const float* __restrict__ locs, int N)
{
    extern __shared__ float shf[];
    float*          s_loc   = shf;                               // [NMAX*3]
    int*            s_cnt   = (int*)(s_loc + NMAX * 3);          // [BCELLS]
    int*            s_start = s_cnt + BCELLS;                    // [BCELLS+1]
    unsigned short* s_bkt   = (unsigned short*)(s_start + BCELLS + 1);

    __shared__ float s_wmn[32][3], s_wmx[32][3];
    __shared__ int   s_part[1024];
    __shared__ float s_lo[3], s_hi[3];

    const int b = blockIdx.x;
    const int t = threadIdx.x;
    const int lane = t & 31;
    const int wid  = t >> 5;

    // ---- 0) stage locs into smem, coalesced float4 ----
    {
        const float* Lg = locs + (size_t)b * N * 3;
        int n4 = (N * 3) >> 2;
        const float4* L4 = (const float4*)Lg;
        float4* S4 = (float4*)s_loc;
        for (int k = t; k < n4; k += 1024) S4[k] = L4[k];
        for (int k = (n4 << 2) + t; k < N * 3; k += 1024) s_loc[k] = Lg[k];
    }
    __syncthreads();

    // ---- 1) min/max, warp shuffles ----
    float mn[3] = { FLT_MAX, FLT_MAX, FLT_MAX };
    float mx[3] = { -FLT_MAX, -FLT_MAX, -FLT_MAX };
    for (int i = t; i < N; i += 1024) {
        #pragma unroll
        for (int d = 0; d < 3; d++) {
            float v = s_loc[i * 3 + d];
            mn[d] = fminf(mn[d], v);
            mx[d] = fmaxf(mx[d], v);
        }
    }
    #pragma unroll
    for (int d = 0; d < 3; d++) {
        #pragma unroll
        for (int o = 16; o > 0; o >>= 1) {
            mn[d] = fminf(mn[d], __shfl_down_sync(0xffffffffu, mn[d], o));
            mx[d] = fmaxf(mx[d], __shfl_down_sync(0xffffffffu, mx[d], o));
        }
        if (lane == 0) { s_wmn[wid][d] = mn[d]; s_wmx[wid][d] = mx[d]; }
    }
    __syncthreads();
    if (wid == 0) {
        float a[3], z[3];
        #pragma unroll
        for (int d = 0; d < 3; d++) { a[d] = s_wmn[lane][d]; z[d] = s_wmx[lane][d]; }
        #pragma unroll
        for (int d = 0; d < 3; d++) {
            #pragma unroll
            for (int o = 16; o > 0; o >>= 1) {
                a[d] = fminf(a[d], __shfl_down_sync(0xffffffffu, a[d], o));
                z[d] = fmaxf(z[d], __shfl_down_sync(0xffffffffu, z[d], o));
            }
            if (lane == 0) { s_lo[d] = a[d]; s_hi[d] = z[d]; }
        }
    }
    __syncthreads();

    // grid info (redundant per-thread; deterministic)
    int g[3];
    #pragma unroll
    for (int d = 0; d < 3; d++) {
        int gg = (int)floorf(__fdiv_rn(__fsub_rn(s_hi[d], s_lo[d]), RAD)) + 1;
        g[d] = max(1, min(GMAX, gg));
    }
    const int st1 = g[2];
    const int st0 = g[1] * g[2];
    int gdp = g[0] * g[1] * g[2];
    if (gdp > BCELLS) gdp = BCELLS;     // never hit for [0,1)^3 data (gdp=1000)
    if (t == 0) {
        GridInfo gi;
        gi.lx = s_lo[0]; gi.ly = s_lo[1]; gi.lz = s_lo[2];
        gi.g0 = g[0]; gi.g1 = g[1]; gi.g2 = g[2];
        gi.s0 = st0; gi.s1 = st1; gi.gdprod = gdp;
        g_grid[b] = gi;
    }

    // ---- 2) zero counters ----
    for (int c = t; c < gdp; c += 1024) s_cnt[c] = 0;
    __syncthreads();

    // ---- 3) cid + bucket scatter (the ONLY atomic pass) ----
    for (int i = t; i < N; i += 1024) {
        int c[3];
        #pragma unroll
        for (int d = 0; d < 3; d++) {
            float v = s_loc[i * 3 + d];
            int cc = (int)floorf(__fdiv_rn(__fsub_rn(v, s_lo[d]), RAD));
            cc = max(0, min(g[d] - 1, cc));
            c[d] = cc;
        }
        int cid = c[0] * st0 + c[1] * st1 + c[2];
        if (cid >= gdp) cid = gdp - 1;  // only if gdp was clamped
        int slot = atomicAdd(&s_cnt[cid], 1);
        if (slot < BCAP) s_bkt[cid * BCAP + slot] = (unsigned short)i;
    }
    __syncthreads();

    // ---- 4) exclusive scan over counters -> s_start ----
    if (gdp <= 1024) {
        int v = (t < gdp) ? s_cnt[t] : 0;
        int x = v;
        #pragma unroll
        for (int o = 1; o < 32; o <<= 1) {
            int y = __shfl_up_sync(0xffffffffu, x, o);
            if (lane >= o) x += y;
        }
        if (lane == 31) s_part[wid] = x;
        __syncthreads();
        if (wid == 0) {
            int w = s_part[lane];
            int xw = w;
            #pragma unroll
            for (int o = 1; o < 32; o <<= 1) {
                int y = __shfl_up_sync(0xffffffffu, xw, o);
                if (lane >= o) xw += y;
            }
            s_part[lane] = xw - w;
        }
        __syncthreads();
        int excl = x - v + s_part[wid];
        if (t < gdp) s_start[t] = excl;
        if (t == 0) s_start[gdp] = N;
        __syncthreads();
    } else {
        const int E = (gdp + 1023) >> 10;   // <= 2 for BCELLS=1728
        int vals[2];
        int base = t * E;
        int sum = 0;
        #pragma unroll 2
        for (int e = 0; e < 2; e++) {
            int c = base + e;
            int v = (e < E && c < gdp) ? s_cnt[c] : 0;
            vals[e] = v; sum += v;
        }
        s_part[t] = sum;
        __syncthreads();
        for (int off = 1; off < 1024; off <<= 1) {
            int v = (t >= off) ? s_part[t - off] : 0;
            __syncthreads();
            s_part[t] += v;
            __syncthreads();
        }
        int run = s_part[t] - sum;
        #pragma unroll 2
        for (int e = 0; e < 2; e++) {
            int c = base + e;
            if (e < E && c < gdp) { s_start[c] = run; run += vals[e]; }
        }
        if (t == 0) s_start[gdp] = N;
        __syncthreads();
    }

    // emit g_start[0..gdp] (collide cells are bounds-guarded by g0/g1/g2)
    for (int c = t; c <= gdp; c += 1024)
        g_start[b][c] = s_start[c];

    // ---- 5) per-cell insertion sort (ascending original index => exact
    //         STABLE order) + emit g_idx / g_nlocs ----
    for (int c = t; c < gdp; c += 1024) {
        unsigned short* bk = s_bkt + c * BCAP;
        int n = min(s_cnt[c], BCAP);
        for (int i = 1; i < n; i++) {
            unsigned short v = bk[i];
            int j = i - 1;
            while (j >= 0 && bk[j] > v) { bk[j + 1] = bk[j]; j--; }
            bk[j + 1] = v;
        }
        int base = s_start[c];
        for (int k = 0; k < n; k++) {
            int i = bk[k];
            int pos = base + k;
            g_idx[b][pos] = i;
            float x = s_loc[i * 3 + 0];
            float y = s_loc[i * 3 + 1];
            float z = s_loc[i * 3 + 2];
            g_nlocs[b][pos] = make_float4(x, y, z, 0.f);
        }
    }
}

// ---------------------------------------------------------------------------
// Fused tail: [collide blocks | emit blocks | gather blocks]
// Collide: minimal-register segment loop; early-exit bookkeeping removed
// (writes are pos<KMAX guarded => identical output, fewer instructions).
// ---------------------------------------------------------------------------
__global__ void tail_kernel(const float4* __restrict__ data,
                            const float* __restrict__ qlocs,
                            float* __restrict__ out_nlocs,
                            float4* __restrict__ out_ndata,
                            float* __restrict__ out_idxs,
                            float* __restrict__ out_nb,
                            int B, int N, int C4, int M,
                            int collideBlocks, int emitBlocks)
{
    int bx = blockIdx.x;
    if (bx >= collideBlocks) {
        bx -= collideBlocks;
        if (bx < emitBlocks) {
            // -------- emit out_idxs + out_nlocs from g_idx/g_nlocs --------
            int t = bx * blockDim.x + threadIdx.x;
            if (t >= B * N) return;
            int b = t / N, pos = t - b * N;
            float4 p = g_nlocs[b][pos];
            float* o = out_nlocs + (size_t)t * 3;
            o[0] = p.x; o[1] = p.y; o[2] = p.z;
            out_idxs[t] = (float)__ldg(&g_idx[b][pos]);
            return;
        }
        // ---------------- gather: 4 float4s per thread ----------------
        int Q = C4 >> 2;
        int t = (bx - emitBlocks) * blockDim.x + threadIdx.x;
        if (t >= B * N * Q) return;
        int sub = t % Q;
        int bi  = t / Q;
        int b = bi / N, i = bi - b * N;
        int idx = __ldg(&g_idx[b][i]);
        const float4* src = data + (((size_t)b * N + idx) * C4) + sub * 4;
        float4* dst = out_ndata + ((size_t)bi * C4) + sub * 4;
        float4 v0 = src[0], v1 = src[1], v2 = src[2], v3 = src[3];
        dst[0] = v0; dst[1] = v1; dst[2] = v2; dst[3] = v3;
        return;
    }

    // ---------------- collide: one warp per query ----------------
    int gt   = blockIdx.x * blockDim.x + threadIdx.x;
    int w    = gt >> 5;
    int lane = gt & 31;
    if (w >= B * M) return;
    int b = w / M, m = w - b * M;

    const float* q = qlocs + ((size_t)b * M + m) * 3;
    float qx = q[0], qy = q[1], qz = q[2];

    GridInfo gi = g_grid[b];
    int cqx = (int)floorf(__fdiv_rn(__fsub_rn(qx, gi.lx), RAD));
    int cqy = (int)floorf(__fdiv_rn(__fsub_rn(qy, gi.ly), RAD));
    int cqz = (int)floorf(__fdiv_rn(__fsub_rn(qz, gi.lz), RAD));
    int z0 = max(0, cqz - 1), z1 = min(gi.g2 - 1, cqz + 1);

    const int* __restrict__ S = g_start[b];
    const float4* __restrict__ P = g_nlocs[b];
    float* outp = out_nb + (size_t)w * KMAX;

    // prefill whole row with -1 (one float4 per lane), hits overwrite below
    ((float4*)outp)[lane] = make_float4(-1.f, -1.f, -1.f, -1.f);
    __syncwarp();

    // segment bounds (18 concurrent LDGs, fully unrolled predicated)
    int jlo[9], jhi[9];
    bool zok = (z0 <= z1);
    #pragma unroll
    for (int r = 0; r < 9; r++) {
        int cx = cqx + (r / 3) - 1;
        int cy = cqy + (r % 3) - 1;
        bool ok = zok && cx >= 0 && cx < gi.g0 && cy >= 0 && cy < gi.g1;
        int base = cx * gi.s0 + cy * gi.s1;
        jlo[r] = ok ? S[base + z0] : 0;
        jhi[r] = ok ? S[base + z1 + 1] : 0;
    }

    int cnt = 0;
    #pragma unroll
    for (int r = 0; r < 9; r++) {
        int lo = jlo[r], hi = jhi[r];
        for (int j0 = lo; j0 < hi; j0 += 32) {
            int j = j0 + lane;
            bool hit = false;
            if (j < hi) {
                float4 p = P[j];
                float dx = __fsub_rn(qx, p.x);
                float dy = __fsub_rn(qy, p.y);
                float dz = __fsub_rn(qz, p.z);
                float d2 = __fadd_rn(__fadd_rn(__fmul_rn(dx, dx),
                                               __fmul_rn(dy, dy)),
                                     __fmul_rn(dz, dz));
                hit = (d2 <= RAD2);
            }
            unsigned msk = __ballot_sync(0xffffffffu, hit);
            if (hit) {
                int pos = cnt + __popc(msk & ((1u << lane) - 1u));
                if (pos < KMAX) outp[pos] = (float)j;
            }
            cnt += __popc(msk);
        }
    }
}

// ---------------------------------------------------------------------------
extern "C" void kernel_launch(void* const* d_in, const int* in_sizes, int n_in,
                              void* d_out, int out_size)
{
    const float* locs  = (const float*)d_in[0];
    const float* data  = (const float*)d_in[1];
    const float* qlocs = (const float*)d_in[2];

    const int B = 2;                       // fixed by setup_inputs
    const int N = in_sizes[0] / (B * 3);
    const int C = in_sizes[1] / (B * N);
    const int M = in_sizes[2] / (B * 3);
    if (N > NMAX || B > BMAX) return;      // scratch bound guard (never hit)

    float* out       = (float*)d_out;
    float* out_nlocs = out;
    float* out_ndata = out_nlocs + (size_t)B * N * 3;
    float* out_idxs  = out_ndata + (size_t)B * N * C;
    float* out_nb    = out_idxs  + (size_t)B * N;

    size_t smem = (size_t)NMAX * 3 * sizeof(float)
                + (size_t)(BCELLS + BCELLS + 1) * sizeof(int)
                + (size_t)BCELLS * BCAP * sizeof(unsigned short);
    cudaFuncSetAttribute(sort_kernel,
                         cudaFuncAttributeMaxDynamicSharedMemorySize, (int)smem);
    sort_kernel<<<B, 1024, smem>>>(locs, N);

    const int TPB = 256;
    int C4 = C / 4;
    int Q  = C4 / 4;
    int collideBlocks = (B * M * 32 + TPB - 1) / TPB;
    int emitBlocks    = (B * N + TPB - 1) / TPB;
    int gatherBlocks  = (B * N * Q + TPB - 1) / TPB;
    tail_kernel<<<collideBlocks + emitBlocks + gatherBlocks, TPB>>>(
        (const float4*)data, qlocs, out_nlocs, (float4*)out_ndata,
        out_idxs, out_nb, B, N, C4, M, collideBlocks, emitBlocks);
}

// round 17
// speedup vs baseline: 1.4092x; 1.2221x over previous
#include <cuda_runtime.h>
#include <math.h>
#include <float.h>

// Problem constants (fixed by setup_inputs)
#define BMAX 2
#define NMAX 8192
#define GMAX 96
#define KMAX 128
#define RAD  0.1f
#define RAD2 0.01f      // float32 nearest to python 0.1*0.1 (matches JAX)
#define CMAXF 8192      // max flattened cells supported (data -> gdprod = 1000)

struct GridInfo {
    float lx, ly, lz;
    int g0, g1, g2;
    int s0, s1;
    int gdprod;
};

__device__ GridInfo g_grid[BMAX];
__device__ int      g_idx[BMAX][NMAX];
__device__ float4   g_nlocs[BMAX][NMAX];
__device__ int      g_start[BMAX][CMAXF + 1];

// ---------------------------------------------------------------------------
// Fused sort kernel (R9/R10 champion, verbatim): one block per batch, 1024
// threads, all phases in smem. Emits g_idx / g_nlocs / g_start only.
// smem: loc[3N] | cid[N] | idx[N] | start[CMAXF+1]  (~192KB dynamic)
// ---------------------------------------------------------------------------
__global__ __launch_bounds__(1024)
void sort_kernel(const float* __restrict__ locs, int N)
{
    extern __shared__ float shf[];
    float* s_loc  = shf;                          // [NMAX*3]
    int*  s_cid   = (int*)(s_loc + NMAX * 3);     // [NMAX]
    int*  s_idx   = s_cid + NMAX;                 // [NMAX]
    int*  s_start = s_idx + NMAX;                 // [CMAXF+1]
    int*  s_part  = s_idx;                        // alias: scan partials

    __shared__ float s_wmn[32][3], s_wmx[32][3];
    __shared__ float s_lo[3], s_hi[3];

    const int b = blockIdx.x;
    const int t = threadIdx.x;
    const int lane = t & 31;
    const int wid  = t >> 5;

    // ---- 0) stage locs into smem, coalesced float4 ----
    {
        const float* Lg = locs + (size_t)b * N * 3;
        int n4 = (N * 3) >> 2;
        const float4* L4 = (const float4*)Lg;
        float4* S4 = (float4*)s_loc;
        for (int k = t; k < n4; k += 1024) S4[k] = L4[k];
        for (int k = (n4 << 2) + t; k < N * 3; k += 1024) s_loc[k] = Lg[k];
    }
    __syncthreads();

    // ---- 1) min/max, warp shuffles ----
    float mn[3] = { FLT_MAX, FLT_MAX, FLT_MAX };
    float mx[3] = { -FLT_MAX, -FLT_MAX, -FLT_MAX };
    for (int i = t; i < N; i += 1024) {
        #pragma unroll
        for (int d = 0; d < 3; d++) {
            float v = s_loc[i * 3 + d];
            mn[d] = fminf(mn[d], v);
            mx[d] = fmaxf(mx[d], v);
        }
    }
    #pragma unroll
    for (int d = 0; d < 3; d++) {
        #pragma unroll
        for (int o = 16; o > 0; o >>= 1) {
            mn[d] = fminf(mn[d], __shfl_down_sync(0xffffffffu, mn[d], o));
            mx[d] = fmaxf(mx[d], __shfl_down_sync(0xffffffffu, mx[d], o));
        }
        if (lane == 0) { s_wmn[wid][d] = mn[d]; s_wmx[wid][d] = mx[d]; }
    }
    __syncthreads();
    if (wid == 0) {
        float a[3], z[3];
        #pragma unroll
        for (int d = 0; d < 3; d++) { a[d] = s_wmn[lane][d]; z[d] = s_wmx[lane][d]; }
        #pragma unroll
        for (int d = 0; d < 3; d++) {
            #pragma unroll
            for (int o = 16; o > 0; o >>= 1) {
                a[d] = fminf(a[d], __shfl_down_sync(0xffffffffu, a[d], o));
                z[d] = fmaxf(z[d], __shfl_down_sync(0xffffffffu, z[d], o));
            }
            if (lane == 0) { s_lo[d] = a[d]; s_hi[d] = z[d]; }
        }
    }
    __syncthreads();

    // grid info (redundant per-thread; deterministic)
    int g[3];
    #pragma unroll
    for (int d = 0; d < 3; d++) {
        int gg = (int)floorf(__fdiv_rn(__fsub_rn(s_hi[d], s_lo[d]), RAD)) + 1;
        g[d] = max(1, min(GMAX, gg));
    }
    const int st1 = g[2];
    const int st0 = g[1] * g[2];
    int gdp = g[0] * g[1] * g[2];
    if (gdp > CMAXF) gdp = CMAXF;       // never hit for [0,1)^3 data
    if (t == 0) {
        GridInfo gi;
        gi.lx = s_lo[0]; gi.ly = s_lo[1]; gi.lz = s_lo[2];
        gi.g0 = g[0]; gi.g1 = g[1]; gi.g2 = g[2];
        gi.s0 = st0; gi.s1 = st1; gi.gdprod = gdp;
        g_grid[b] = gi;
    }

    // ---- 2) zero bins, cell ids, histogram ----
    for (int c = t; c < gdp; c += 1024) s_start[c] = 0;
    __syncthreads();
    for (int i = t; i < N; i += 1024) {
        int c[3];
        #pragma unroll
        for (int d = 0; d < 3; d++) {
            float v = s_loc[i * 3 + d];
            int cc = (int)floorf(__fdiv_rn(__fsub_rn(v, s_lo[d]), RAD));
            cc = max(0, min(g[d] - 1, cc));
            c[d] = cc;
        }
        int cid = c[0] * st0 + c[1] * st1 + c[2];
        if (cid >= gdp) cid = gdp - 1;
        s_cid[i] = cid;
        atomicAdd(&s_start[cid], 1);
    }
    __syncthreads();

    // ---- 3) exclusive scan ----
    if (gdp <= 1024) {
        int v = (t < gdp) ? s_start[t] : 0;
        int x = v;
        #pragma unroll
        for (int o = 1; o < 32; o <<= 1) {
            int y = __shfl_up_sync(0xffffffffu, x, o);
            if (lane >= o) x += y;
        }
        if (lane == 31) s_part[wid] = x;
        __syncthreads();
        if (wid == 0) {
            int w = s_part[lane];
            int xw = w;
            #pragma unroll
            for (int o = 1; o < 32; o <<= 1) {
                int y = __shfl_up_sync(0xffffffffu, xw, o);
                if (lane >= o) xw += y;
            }
            s_part[lane] = xw - w;
        }
        __syncthreads();
        int excl = x - v + s_part[wid];
        __syncthreads();
        if (t < gdp) s_start[t] = excl;
        if (t == 0) s_start[gdp] = N;
        __syncthreads();
    } else {
        const int E = (gdp + 1023) >> 10;
        int vals[8];
        int base = t * E;
        int sum = 0;
        #pragma unroll 8
        for (int e = 0; e < 8; e++) {
            int c = base + e;
            int v = (e < E && c < gdp) ? s_start[c] : 0;
            vals[e] = v; sum += v;
        }
        s_part[t] = sum;
        __syncthreads();
        for (int off = 1; off < 1024; off <<= 1) {
            int v = (t >= off) ? s_part[t - off] : 0;
            __syncthreads();
            s_part[t] += v;
            __syncthreads();
        }
        int run = s_part[t] - sum;
        #pragma unroll 8
        for (int e = 0; e < 8; e++) {
            int c = base + e;
            if (e < E && c < gdp) { s_start[c] = run; run += vals[e]; }
        }
        if (t == 0) s_start[gdp] = N;
        __syncthreads();
    }

    // emit g_start[0..gdp]
    for (int c = t; c <= gdp; c += 1024)
        g_start[b][c] = s_start[c];
    __syncthreads();

    // ---- 4) scatter on s_start: afterwards s_start[c] = start[c+1] ----
    for (int i = t; i < N; i += 1024) {
        int pos = atomicAdd(&s_start[s_cid[i]], 1);
        s_idx[pos] = i;
    }
    __syncthreads();

    // ---- 5) per-cell insertion sort by original index => exact STABLE ----
    for (int c = t; c < gdp; c += 1024) {
        int lo = (c == 0) ? 0 : s_start[c - 1];
        int hi = s_start[c];
        for (int i = lo + 1; i < hi; i++) {
            int v = s_idx[i];
            int j = i - 1;
            while (j >= lo && s_idx[j] > v) { s_idx[j + 1] = s_idx[j]; j--; }
            s_idx[j + 1] = v;
        }
    }
    __syncthreads();

    // ---- 6) emit g_idx + g_nlocs (coalesced per-position) ----
    for (int pos = t; pos < N; pos += 1024) {
        int i = s_idx[pos];
        g_idx[b][pos] = i;
        float x = s_loc[i * 3 + 0];
        float y = s_loc[i * 3 + 1];
        float z = s_loc[i * 3 + 2];
        g_nlocs[b][pos] = make_float4(x, y, z, 0.f);
    }
}

// ---------------------------------------------------------------------------
// Fused tail: [collide blocks | emit blocks | gather blocks]
// Collide: 64-wide rounds — each lane tests j0+lane and j0+32+lane with two
// concurrent clamped loads + two ballots; exact ascending-j ordered append.
// ---------------------------------------------------------------------------
__global__ void tail_kernel(const float4* __restrict__ data,
                            const float* __restrict__ qlocs,
                            float* __restrict__ out_nlocs,
                            float4* __restrict__ out_ndata,
                            float* __restrict__ out_idxs,
                            float* __restrict__ out_nb,
                            int B, int N, int C4, int M,
                            int collideBlocks, int emitBlocks)
{
    int bx = blockIdx.x;
    if (bx >= collideBlocks) {
        bx -= collideBlocks;
        if (bx < emitBlocks) {
            // -------- emit out_idxs + out_nlocs from g_idx/g_nlocs --------
            int t = bx * blockDim.x + threadIdx.x;
            if (t >= B * N) return;
            int b = t / N, pos = t - b * N;
            float4 p = g_nlocs[b][pos];
            float* o = out_nlocs + (size_t)t * 3;
            o[0] = p.x; o[1] = p.y; o[2] = p.z;
            out_idxs[t] = (float)__ldg(&g_idx[b][pos]);
            return;
        }
        // ---------------- gather: 4 float4s per thread ----------------
        int Q = C4 >> 2;
        int t = (bx - emitBlocks) * blockDim.x + threadIdx.x;
        if (t >= B * N * Q) return;
        int sub = t % Q;
        int bi  = t / Q;
        int b = bi / N, i = bi - b * N;
        int idx = __ldg(&g_idx[b][i]);
        const float4* src = data + (((size_t)b * N + idx) * C4) + sub * 4;
        float4* dst = out_ndata + ((size_t)bi * C4) + sub * 4;
        float4 v0 = src[0], v1 = src[1], v2 = src[2], v3 = src[3];
        dst[0] = v0; dst[1] = v1; dst[2] = v2; dst[3] = v3;
        return;
    }

    // ---------------- collide: one warp per query ----------------
    int gt   = blockIdx.x * blockDim.x + threadIdx.x;
    int w    = gt >> 5;
    int lane = gt & 31;
    if (w >= B * M) return;
    int b = w / M, m = w - b * M;

    const float* q = qlocs + ((size_t)b * M + m) * 3;
    float qx = q[0], qy = q[1], qz = q[2];

    GridInfo gi = g_grid[b];
    int cqx = (int)floorf(__fdiv_rn(__fsub_rn(qx, gi.lx), RAD));
    int cqy = (int)floorf(__fdiv_rn(__fsub_rn(qy, gi.ly), RAD));
    int cqz = (int)floorf(__fdiv_rn(__fsub_rn(qz, gi.lz), RAD));
    int z0 = max(0, cqz - 1), z1 = min(gi.g2 - 1, cqz + 1);

    const int* __restrict__ S = g_start[b];
    const float4* __restrict__ P = g_nlocs[b];
    float* outp = out_nb + (size_t)w * KMAX;

    // prefill whole row with -1 (one float4 per lane), hits overwrite below
    ((float4*)outp)[lane] = make_float4(-1.f, -1.f, -1.f, -1.f);
    __syncwarp();

    // segment bounds (18 concurrent LDGs, fully unrolled predicated)
    int jlo[9], jhi[9];
    bool zok = (z0 <= z1);
    #pragma unroll
    for (int r = 0; r < 9; r++) {
        int cx = cqx + (r / 3) - 1;
        int cy = cqy + (r % 3) - 1;
        bool ok = zok && cx >= 0 && cx < gi.g0 && cy >= 0 && cy < gi.g1;
        int base = cx * gi.s0 + cy * gi.s1;
        jlo[r] = ok ? S[base + z0] : 0;
        jhi[r] = ok ? S[base + z1 + 1] : 0;
    }

    const int nclamp = N - 1;
    int cnt = 0;
    #pragma unroll
    for (int r = 0; r < 9; r++) {
        int lo = jlo[r], hi = jhi[r];
        for (int j0 = lo; j0 < hi; j0 += 64) {
            int ja = j0 + lane;
            int jb = ja + 32;
            bool va = (ja < hi), vb = (jb < hi);
            // two concurrent clamped loads (always in-bounds; hit gated on va/vb)
            float4 pa = P[min(ja, nclamp)];
            float4 pb = P[min(jb, nclamp)];

            float dxa = __fsub_rn(qx, pa.x);
            float dya = __fsub_rn(qy, pa.y);
            float dza = __fsub_rn(qz, pa.z);
            float d2a = __fadd_rn(__fadd_rn(__fmul_rn(dxa, dxa),
                                            __fmul_rn(dya, dya)),
                                  __fmul_rn(dza, dza));
            float dxb = __fsub_rn(qx, pb.x);
            float dyb = __fsub_rn(qy, pb.y);
            float dzb = __fsub_rn(qz, pb.z);
            float d2b = __fadd_rn(__fadd_rn(__fmul_rn(dxb, dxb),
                                            __fmul_rn(dyb, dyb)),
                                  __fmul_rn(dzb, dzb));
            bool hita = va && (d2a <= RAD2);
            bool hitb = vb && (d2b <= RAD2);

            unsigned ma = __ballot_sync(0xffffffffu, hita);
            unsigned mb = __ballot_sync(0xffffffffu, hitb);
            unsigned below = (1u << lane) - 1u;
            if (hita) {
                int pos = cnt + __popc(ma & below);
                if (pos < KMAX) outp[pos] = (float)ja;
            }
            int ca = __popc(ma);
            if (hitb) {
                int pos = cnt + ca + __popc(mb & below);
                if (pos < KMAX) outp[pos] = (float)jb;
            }
            cnt += ca + __popc(mb);
        }
    }
}

// ---------------------------------------------------------------------------
extern "C" void kernel_launch(void* const* d_in, const int* in_sizes, int n_in,
                              void* d_out, int out_size)
{
    const float* locs  = (const float*)d_in[0];
    const float* data  = (const float*)d_in[1];
    const float* qlocs = (const float*)d_in[2];

    const int B = 2;                       // fixed by setup_inputs
    const int N = in_sizes[0] / (B * 3);
    const int C = in_sizes[1] / (B * N);
    const int M = in_sizes[2] / (B * 3);
    if (N > NMAX || B > BMAX) return;      // scratch bound guard (never hit)

    float* out       = (float*)d_out;
    float* out_nlocs = out;
    float* out_ndata = out_nlocs + (size_t)B * N * 3;
    float* out_idxs  = out_ndata + (size_t)B * N * C;
    float* out_nb    = out_idxs  + (size_t)B * N;

    size_t smem = (size_t)(NMAX * 3 + NMAX * 2 + (CMAXF + 1)) * sizeof(float);
    cudaFuncSetAttribute(sort_kernel,
                         cudaFuncAttributeMaxDynamicSharedMemorySize, (int)smem);
    sort_kernel<<<B, 1024, smem>>>(locs, N);

    const int TPB = 256;
    int C4 = C / 4;
    int Q  = C4 / 4;
    int collideBlocks = (B * M * 32 + TPB - 1) / TPB;
    int emitBlocks    = (B * N + TPB - 1) / TPB;
    int gatherBlocks  = (B * N * Q + TPB - 1) / TPB;
    tail_kernel<<<collideBlocks + emitBlocks + gatherBlocks, TPB>>>(
        (const float4*)data, qlocs, out_nlocs, (float4*)out_ndata,
        out_idxs, out_nb, B, N, C4, M, collideBlocks, emitBlocks);
}